// round 1
// baseline (speedup 1.0000x reference)
#include <cuda_runtime.h>

// ISTSimulator: B=65536, V=2, L=200 sequential recurrence per (b,v) lane.
// in:  (B, 14, 1) fp32  -> params for lane tid=(b*2+v) at in[7*tid .. 7*tid+6]
// out: (B, 400)   fp32  -> lane tid writes out[200*tid .. 200*tid+199]

#define LOG2E_F 1.4426950408889634f

__device__ __forceinline__ float ex2a(float x) {
    float r; asm("ex2.approx.ftz.f32 %0, %1;" : "=f"(r) : "f"(x)); return r;
}
__device__ __forceinline__ float lg2a(float x) {
    float r; asm("lg2.approx.f32 %0, %1;" : "=f"(r) : "f"(x)); return r;
}
__device__ __forceinline__ float rcpa(float x) {
    float r; asm("rcp.approx.ftz.f32 %0, %1;" : "=f"(r) : "f"(x)); return r;
}

__global__ void __launch_bounds__(256) ist_sim_kernel(
    const float* __restrict__ in, float* __restrict__ out, int n_lanes)
{
    int tid = blockIdx.x * blockDim.x + threadIdx.x;
    if (tid >= n_lanes) return;

    const float* p = in + tid * 7;
    float lam  = 0.001f * fmaxf(p[0], 0.0f);
    float beta = fmaf(10.0f, fmaxf(p[1], 0.0f), 1.0f);
    float kd   = p[2];
    float mu   = p[3];
    float kf   = p[4];
    float nc   = p[5];
    float wt   = p[6];

    // sigmoid((n - nc)/wt) = 1 / (1 + 2^((nc - n) * a)),  a = log2(e)/wt
    float a  = LOG2E_F / wt;
    float z0 = nc * a;

    float D = 0.0f;
    float F = 1e-12f;
    float nf = 0.0f;

    float* o = out + tid * 200;

    #pragma unroll 1
    for (int n4 = 0; n4 < 200; n4 += 4) {
        float4 r;
        float* rv = &r.x;
        #pragma unroll
        for (int j = 0; j < 4; ++j) {
            // D update: D = min(D + lam * (1-D)^beta, 1-eps)  [1-1e-12 == 1.0f in fp32]
            float omd = fmaxf(1.0f - D, 1e-12f);
            float pw  = ex2a(beta * lg2a(omd));
            D = fminf(fmaf(lam, pw, D), 1.0f);

            // g = sigmoid((n - nc)/wt)
            float z = fmaf(nf, -a, z0);     // (nc - n) * a, exact nf
            float e = ex2a(z);
            float g = rcpa(1.0f + e);

            // F = clip(F + g*(mu*F + eps), 0, 1-eps)
            float t  = fmaf(mu, F, 1e-12f);
            float Fn = fmaf(g, t, F);
            F = fminf(fmaxf(Fn, 0.0f), 1.0f);

            rv[j] = fmaf(kd, D, kf * F);
            nf += 1.0f;
        }
        *reinterpret_cast<float4*>(o + n4) = r;
    }
}

extern "C" void kernel_launch(void* const* d_in, const int* in_sizes, int n_in,
                              void* d_out, int out_size)
{
    const float* in = (const float*)d_in[0];
    float* out = (float*)d_out;
    int n_lanes = in_sizes[0] / 7;      // B * 2 lanes (14 params per b = 7 per lane)
    int threads = 256;
    int blocks = (n_lanes + threads - 1) / threads;
    ist_sim_kernel<<<blocks, threads>>>(in, out, n_lanes);
}